// round 9
// baseline (speedup 1.0000x reference)
#include <cuda_runtime.h>
#include <math.h>

#define NUM_TOKENS 16384
#define D_MODEL    2048
#define NUM_EXP    8
#define D4         512                    // float4 per token row
#define THREADS    512
#define WARPS      16
#define NUM_CTAS   296                    // 2 per SM x 148 SMs, exactly one wave
#define TOTAL_WARPS (NUM_CTAS * WARPS)    // 4736
#define TOK_PER_UNIT 2
#define NUM_UNITS  (NUM_TOKENS / TOK_PER_UNIT)   // 8192
#define ITERS      16                     // 512 f4-cols / 32 lanes

// ---- Blackwell packed fp32x2 helpers ----
__device__ __forceinline__ void fma2(unsigned long long& d,
                                     unsigned long long a,
                                     unsigned long long b)
{
    asm("fma.rn.f32x2 %0, %1, %2, %0;" : "+l"(d) : "l"(a), "l"(b));
}
__device__ __forceinline__ unsigned long long add2(unsigned long long a,
                                                   unsigned long long b)
{
    unsigned long long r;
    asm("add.rn.f32x2 %0, %1, %2;" : "=l"(r) : "l"(a), "l"(b));
    return r;
}
__device__ __forceinline__ unsigned long long bcast2(float v)
{
    unsigned long long r;
    asm("mov.b64 %0, {%1, %1};" : "=l"(r) : "f"(v));
    return r;
}
__device__ __forceinline__ float2 unpack2(unsigned long long v)
{
    float2 f;
    asm("mov.b64 {%0, %1}, %2;" : "=f"(f.x), "=f"(f.y) : "l"(v));
    return f;
}

// smem: W expert-pair interleaved f32x2, lo 32KB | hi 32KB = 64 KB
extern __shared__ float4 sm4[];
#define SW_LO 0
#define SW_HI (4 * D4)

__global__ __launch_bounds__(THREADS, 2)
void gate_kernel(const float* __restrict__ x,
                 const float* __restrict__ W,
                 float* __restrict__ out,
                 int write_experts)
{
    const int tid  = threadIdx.x;
    const int warp = tid >> 5;
    const int lane = tid & 31;
    const int gw   = blockIdx.x * WARPS + warp;   // global warp id

    // ---- Stage W: expert-pair interleaved, lo/hi split (64 KB) ----
    // (ep, c): lo = (W[2ep][4c],W[2ep+1][4c], W[2ep][4c+1],W[2ep+1][4c+1]); hi = d+2,d+3
    for (int i = tid; i < 4 * D4; i += THREADS) {
        const int ep = i >> 9, c = i & 511;
        const float* w0 = W + (2 * ep)     * D_MODEL + 4 * c;
        const float* w1 = W + (2 * ep + 1) * D_MODEL + 4 * c;
        sm4[SW_LO + i] = make_float4(w0[0], w1[0], w0[1], w1[1]);
        sm4[SW_HI + i] = make_float4(w0[2], w1[2], w0[3], w1[3]);
    }
    __syncthreads();

    const ulonglong2* wlo = reinterpret_cast<const ulonglong2*>(sm4 + SW_LO);
    const ulonglong2* whi = wlo + 4 * D4;   // hi starts 32 KB (= 4*D4 x 16B) in
    const float4* x4 = reinterpret_cast<const float4*>(x);

    // Interleaved unit assignment: unit u handled by warp (u % TOTAL_WARPS).
    for (int u = gw; u < NUM_UNITS; u += TOTAL_WARPS) {
        const int tok0 = u * TOK_PER_UNIT;
        const float4* gx = x4 + (size_t)tok0 * D4 + lane;

        unsigned long long acc[4][TOK_PER_UNIT];   // f32x2 per (expert-pair, token)
        #pragma unroll
        for (int p = 0; p < 4; p++) {
            acc[p][0] = 0ull;
            acc[p][1] = 0ull;
        }

        #pragma unroll 2
        for (int it = 0; it < ITERS; it++) {
            // 2 independent LDG.128
            float4 xv0 = gx[it * 32];
            float4 xv1 = gx[D4 + it * 32];

            unsigned long long a0 = bcast2(xv0.x), a1 = bcast2(xv0.y);
            unsigned long long a2 = bcast2(xv0.z), a3 = bcast2(xv0.w);
            unsigned long long b0 = bcast2(xv1.x), b1 = bcast2(xv1.y);
            unsigned long long b2 = bcast2(xv1.z), b3 = bcast2(xv1.w);

            const int c = it * 32 + lane;
            #pragma unroll
            for (int p = 0; p < 4; p++) {
                ulonglong2 WL = wlo[p * D4 + c];
                ulonglong2 WH = whi[p * D4 + c];
                fma2(acc[p][0], a0, WL.x);
                fma2(acc[p][0], a1, WL.y);
                fma2(acc[p][0], a2, WH.x);
                fma2(acc[p][0], a3, WH.y);
                fma2(acc[p][1], b0, WL.x);
                fma2(acc[p][1], b1, WL.y);
                fma2(acc[p][1], b2, WH.x);
                fma2(acc[p][1], b3, WH.y);
            }
        }

        // ---- warp butterfly reduction on packed accumulators ----
        #pragma unroll
        for (int off = 16; off >= 1; off >>= 1)
            #pragma unroll
            for (int p = 0; p < 4; p++) {
                acc[p][0] = add2(acc[p][0],
                                 __shfl_xor_sync(0xFFFFFFFFu, acc[p][0], off));
                acc[p][1] = add2(acc[p][1],
                                 __shfl_xor_sync(0xFFFFFFFFu, acc[p][1], off));
            }

        if (lane < TOK_PER_UNIT) {
            float logit[NUM_EXP];
            #pragma unroll
            for (int p = 0; p < 4; p++) {
                float2 f = unpack2(lane == 0 ? acc[p][0] : acc[p][1]);
                logit[2 * p]     = f.x;
                logit[2 * p + 1] = f.y;
            }

            const int tok = tok0 + lane;

            // top-2 scan; strict '>' keeps lowest index on ties (JAX top_k)
            float v1 = logit[0], v2 = -INFINITY;
            int   i1 = 0,        i2 = 0;
            #pragma unroll
            for (int e = 1; e < NUM_EXP; e++) {
                float le = logit[e];
                if (le > v1)      { v2 = v1; i2 = i1; v1 = le; i1 = e; }
                else if (le > v2) { v2 = le; i2 = e; }
            }

            // softmax + top-2 + renorm == 2-way softmax over top-2 logits
            float r  = __expf(v2 - v1);
            float w1 = 1.0f / (1.0f + r);
            float w2 = 1.0f - w1;

            out[tok * 2 + 0] = w1;
            out[tok * 2 + 1] = w2;
            if (write_experts) {
                out[2 * NUM_TOKENS + tok * 2 + 0] = (float)i1;
                out[2 * NUM_TOKENS + tok * 2 + 1] = (float)i2;
            }
        }
    }
}

extern "C" void kernel_launch(void* const* d_in, const int* in_sizes, int n_in,
                              void* d_out, int out_size)
{
    const float* x = (const float*)d_in[0];
    const float* W = (const float*)d_in[1];
    float* out = (float*)d_out;

    int write_experts = (out_size >= 4 * NUM_TOKENS) ? 1 : 0;

    const int smem = 8 * D4 * (int)sizeof(float4);   // 64 KB
    cudaFuncSetAttribute(gate_kernel, cudaFuncAttributeMaxDynamicSharedMemorySize, smem);

    gate_kernel<<<NUM_CTAS, THREADS, smem>>>(x, W, out, write_experts);
}

// round 10
// speedup vs baseline: 1.2182x; 1.2182x over previous
#include <cuda_runtime.h>
#include <math.h>

#define NUM_TOKENS 16384
#define D_MODEL    2048
#define NUM_EXP    8
#define D4         512                    // float4 per token row
#define THREADS    512
#define WARPS      16
#define NUM_CTAS   148                    // one CTA per SM, single wave
#define TOTAL_WARPS (NUM_CTAS * WARPS)    // 2368
#define TOK_PER_UNIT 8
#define NUM_UNITS  (NUM_TOKENS / TOK_PER_UNIT)   // 2048
#define ITERS      16                     // 512 f4-cols / 32 lanes

// ---- Blackwell packed fp32x2 helpers ----
__device__ __forceinline__ void fma2(unsigned long long& d,
                                     unsigned long long a,
                                     unsigned long long b)
{
    asm("fma.rn.f32x2 %0, %1, %2, %0;" : "+l"(d) : "l"(a), "l"(b));
}
__device__ __forceinline__ unsigned long long add2(unsigned long long a,
                                                   unsigned long long b)
{
    unsigned long long r;
    asm("add.rn.f32x2 %0, %1, %2;" : "=l"(r) : "l"(a), "l"(b));
    return r;
}
__device__ __forceinline__ unsigned long long bcast2(float v)
{
    unsigned long long r;
    asm("mov.b64 %0, {%1, %1};" : "=l"(r) : "f"(v));
    return r;
}
__device__ __forceinline__ float2 unpack2(unsigned long long v)
{
    float2 f;
    asm("mov.b64 {%0, %1}, %2;" : "=f"(f.x), "=f"(f.y) : "l"(v));
    return f;
}

// smem: W expert-pair interleaved f32x2, lo 32 KB | hi 32 KB = 64 KB
extern __shared__ float4 sm4[];
#define SW_LO 0
#define SW_HI (4 * D4)

__global__ __launch_bounds__(THREADS, 1)
void gate_kernel(const float* __restrict__ x,
                 const float* __restrict__ W,
                 float* __restrict__ out,
                 int write_experts)
{
    const int tid  = threadIdx.x;
    const int warp = tid >> 5;
    const int lane = tid & 31;
    const int gw   = blockIdx.x * WARPS + warp;   // 0..2367

    // ---- Stage W: expert-pair interleaved, lo/hi split (64 KB) ----
    // (ep, c): lo = (W[2ep][4c],W[2ep+1][4c], W[2ep][4c+1],W[2ep+1][4c+1]); hi = d+2,d+3
    for (int i = tid; i < 4 * D4; i += THREADS) {
        const int ep = i >> 9, c = i & 511;
        const float* w0 = W + (2 * ep)     * D_MODEL + 4 * c;
        const float* w1 = W + (2 * ep + 1) * D_MODEL + 4 * c;
        sm4[SW_LO + i] = make_float4(w0[0], w1[0], w0[1], w1[1]);
        sm4[SW_HI + i] = make_float4(w0[2], w1[2], w0[3], w1[3]);
    }
    __syncthreads();

    const ulonglong2* wlo = reinterpret_cast<const ulonglong2*>(sm4 + SW_LO);
    const ulonglong2* whi = wlo + 4 * D4;   // hi starts 32 KB (= 4*D4 x 16B) in
    const float4* x4 = reinterpret_cast<const float4*>(x);

    // Balanced division: warp gw handles units [gw*2048/2368, (gw+1)*2048/2368)
    // -> 0 or 1 units per warp; 13-14 units per CTA.
    const int u0 = (int)(((long long)gw * NUM_UNITS) / TOTAL_WARPS);
    const int u1 = (int)(((long long)(gw + 1) * NUM_UNITS) / TOTAL_WARPS);

    for (int u = u0; u < u1; u++) {
        const int tok0 = u * TOK_PER_UNIT;
        const float4* gx = x4 + (size_t)tok0 * D4 + lane;

        unsigned long long acc[4][TOK_PER_UNIT];  // f32x2 per (expert-pair, token)
        #pragma unroll
        for (int p = 0; p < 4; p++)
            #pragma unroll
            for (int t = 0; t < TOK_PER_UNIT; t++)
                acc[p][t] = 0ull;

        #pragma unroll 2
        for (int it = 0; it < ITERS; it++) {
            // 8 independent streaming LDG.128, front-batched (4 KB in flight)
            float4 xv[TOK_PER_UNIT];
            #pragma unroll
            for (int t = 0; t < TOK_PER_UNIT; t++)
                xv[t] = __ldcs(gx + (size_t)t * D4 + it * 32);

            const int c = it * 32 + lane;
            #pragma unroll
            for (int p = 0; p < 4; p++) {
                ulonglong2 WL = wlo[p * D4 + c];
                ulonglong2 WH = whi[p * D4 + c];
                #pragma unroll
                for (int t = 0; t < TOK_PER_UNIT; t++) {
                    fma2(acc[p][t], bcast2(xv[t].x), WL.x);
                    fma2(acc[p][t], bcast2(xv[t].y), WL.y);
                    fma2(acc[p][t], bcast2(xv[t].z), WH.x);
                    fma2(acc[p][t], bcast2(xv[t].w), WH.y);
                }
            }
        }

        // ---- warp butterfly reduction on packed accumulators ----
        #pragma unroll
        for (int off = 16; off >= 1; off >>= 1)
            #pragma unroll
            for (int p = 0; p < 4; p++)
                #pragma unroll
                for (int t = 0; t < TOK_PER_UNIT; t++)
                    acc[p][t] = add2(acc[p][t],
                                     __shfl_xor_sync(0xFFFFFFFFu, acc[p][t], off));

        // lane t (<8) finalizes token tok0 + t
        float logit[NUM_EXP];
        #pragma unroll
        for (int p = 0; p < 4; p++) {
            unsigned long long v = acc[p][0];
            #pragma unroll
            for (int t = 1; t < TOK_PER_UNIT; t++)
                v = (lane == t) ? acc[p][t] : v;
            float2 f = unpack2(v);
            logit[2 * p]     = f.x;
            logit[2 * p + 1] = f.y;
        }

        if (lane < TOK_PER_UNIT) {
            const int tok = tok0 + lane;

            // top-2 scan; strict '>' keeps lowest index on ties (JAX top_k)
            float v1 = logit[0], v2 = -INFINITY;
            int   i1 = 0,        i2 = 0;
            #pragma unroll
            for (int e = 1; e < NUM_EXP; e++) {
                float le = logit[e];
                if (le > v1)      { v2 = v1; i2 = i1; v1 = le; i1 = e; }
                else if (le > v2) { v2 = le; i2 = e; }
            }

            // softmax + top-2 + renorm == 2-way softmax over top-2 logits
            float r  = __expf(v2 - v1);
            float w1 = 1.0f / (1.0f + r);
            float w2 = 1.0f - w1;

            out[tok * 2 + 0] = w1;
            out[tok * 2 + 1] = w2;
            if (write_experts) {
                out[2 * NUM_TOKENS + tok * 2 + 0] = (float)i1;
                out[2 * NUM_TOKENS + tok * 2 + 1] = (float)i2;
            }
        }
    }
}

extern "C" void kernel_launch(void* const* d_in, const int* in_sizes, int n_in,
                              void* d_out, int out_size)
{
    const float* x = (const float*)d_in[0];
    const float* W = (const float*)d_in[1];
    float* out = (float*)d_out;

    int write_experts = (out_size >= 4 * NUM_TOKENS) ? 1 : 0;

    const int smem = 8 * D4 * (int)sizeof(float4);   // 64 KB
    cudaFuncSetAttribute(gate_kernel, cudaFuncAttributeMaxDynamicSharedMemorySize, smem);

    gate_kernel<<<NUM_CTAS, THREADS, smem>>>(x, W, out, write_experts);
}